// round 14
// baseline (speedup 1.0000x reference)
#include <cuda_runtime.h>

#define BB 8
#define NSEQ 256
#define DD 300
#define KHALF 150
#define MROWS (BB*NSEQ)          // 2048
#define FEATW 512                // left | right | hs | he
#define LRW 256                  // compact left|right width

typedef unsigned long long ull;

// K-half partials (raw), compact combined left|right features
__device__ float g_part0[MROWS * FEATW];
__device__ float g_part1[MROWS * FEATW];
__device__ float g_lr   [MROWS * LRW];   // [row][0:128 left+bl | 128:256 right]

// ---- packed f32x2 helpers (sm_100+) --------------------------------------
__device__ __forceinline__ ull f2_pack(float x, float y) {
    ull r; asm("mov.b64 %0, {%1,%2};" : "=l"(r) : "f"(x), "f"(y)); return r;
}
__device__ __forceinline__ float2 f2_unpack(ull v) {
    float2 r; asm("mov.b64 {%0,%1}, %2;" : "=f"(r.x), "=f"(r.y) : "l"(v)); return r;
}
#define FMA2(d,a,b,c) asm("fma.rn.f32x2 %0, %1, %2, %3;" : "=l"(d) : "l"(a), "l"(b), "l"(c))
#define ADD2(d,a,b)   asm("add.rn.f32x2 %0, %1, %2;"     : "=l"(d) : "l"(a), "l"(b))

// ---------------------------------------------------------------------------
// Kernel 1: fused gather + GEMM partials.  [2048 x 150] @ [150 x 512] x2
// BM=256, BN=32, BK=10 (150 = 15*10), 128 thr, grid (8 m, 16 n, 2 z) = 256.
// 4 CTAs/SM target (occ 25%). Per thread per k: 4 LDS.64 (A pairs) +
// 4 bcast LDS.128 (B dup) + 32 FFMA2 -> fma-bound steady state.
// Warp w owns n [8w,8w+8); lane L owns m rows {2L,2L+1} + 64*i, i=0..3.
// ---------------------------------------------------------------------------
#define GBK 10
#define PADA 262
#define PADB 68

__global__ __launch_bounds__(128, 4) void gemm_kernel(
    const int*   __restrict__ sent, const float* __restrict__ emb,
    const float* __restrict__ Wl,   const float* __restrict__ Wr,
    const float* __restrict__ Ws1,  const float* __restrict__ We1)
{
    __shared__ __align__(16) float As[2][GBK * PADA];  // [k][m 0..255]
    __shared__ __align__(16) float Bs[2][GBK * PADB];  // [k][64 dup]
    __shared__ int rowidx[256];

    const int m0 = blockIdx.x * 256;
    const int nt = blockIdx.y;            // 0..15
    const int z  = blockIdx.z;
    const int kz = z * KHALF;
    const int seg = nt >> 2;              // 0:left 1:right 2:hs 3:he
    const int nl0 = (nt & 3) * 32;

    const float* W;
    if      (seg == 0) W = Wl;
    else if (seg == 1) W = Wr;
    else if (seg == 2) W = Ws1;
    else               W = We1;
    float* gout = z ? g_part1 : g_part0;

    const int tid = threadIdx.x;
    rowidx[tid]       = sent[m0 + tid];
    rowidx[tid + 128] = sent[m0 + tid + 128];
    __syncthreads();

    // register prefetch: A tile 256x10 = 2560 = 20*128; B tile 32x10 = 320
    float aR[20], bR[3];
    #pragma unroll
    for (int i = 0; i < 20; i++) {
        int idx = i * 128 + tid; int m = idx / 10; int k = idx - m * 10;
        aR[i] = emb[(long)rowidx[m] * DD + kz + k];
    }
    #pragma unroll
    for (int i = 0; i < 3; i++) {
        int idx = i * 128 + tid;
        if (idx < 320) { int n = idx / 10; int k = idx - n * 10; bR[i] = W[(nl0 + n) * DD + kz + k]; }
    }

    const int lane = tid & 31;
    const int wid  = tid >> 5;            // warp -> 8 n-columns
    ull acc[4][8];
    #pragma unroll
    for (int i = 0; i < 4; i++)
        #pragma unroll
        for (int n = 0; n < 8; n++) acc[i][n] = 0ull;

    for (int t = 0; t < 15; t++) {
        const int c = t & 1;
        #pragma unroll
        for (int i = 0; i < 20; i++) {
            int idx = i * 128 + tid; int m = idx / 10; int k = idx - m * 10;
            As[c][k * PADA + m] = aR[i];
        }
        #pragma unroll
        for (int i = 0; i < 3; i++) {
            int idx = i * 128 + tid;
            if (idx < 320) { int n = idx / 10; int k = idx - n * 10;
                *(ull*)&Bs[c][k * PADB + 2 * n] = f2_pack(bR[i], bR[i]); }
        }
        __syncthreads();

        // prefetch next tile while computing on this one
        if (t < 14) {
            const int k0 = kz + (t + 1) * GBK;
            #pragma unroll
            for (int i = 0; i < 20; i++) {
                int idx = i * 128 + tid; int m = idx / 10; int k = idx - m * 10;
                aR[i] = emb[(long)rowidx[m] * DD + k0 + k];
            }
            #pragma unroll
            for (int i = 0; i < 3; i++) {
                int idx = i * 128 + tid;
                if (idx < 320) { int n = idx / 10; int k = idx - n * 10; bR[i] = W[(nl0 + n) * DD + k0 + k]; }
            }
        }

        #pragma unroll
        for (int k = 0; k < GBK; k++) {
            const float* ab = &As[c][k * PADA + 2 * lane];
            const ull a0 = *(const ull*)&ab[0];
            const ull a1 = *(const ull*)&ab[64];
            const ull a2 = *(const ull*)&ab[128];
            const ull a3 = *(const ull*)&ab[192];
            const ulonglong2* bp = (const ulonglong2*)&Bs[c][k * PADB + 16 * wid]; // bcast
            const ulonglong2 b01 = bp[0], b23 = bp[1], b45 = bp[2], b67 = bp[3];
            const ull b[8] = {b01.x, b01.y, b23.x, b23.y, b45.x, b45.y, b67.x, b67.y};
            #pragma unroll
            for (int n = 0; n < 8; n++) {
                FMA2(acc[0][n], a0, b[n], acc[0][n]);
                FMA2(acc[1][n], a1, b[n], acc[1][n]);
                FMA2(acc[2][n], a2, b[n], acc[2][n]);
                FMA2(acc[3][n], a3, b[n], acc[3][n]);
            }
        }
        __syncthreads();   // buffer c will be overwritten at t+2's staging
    }

    // epilogue: raw partial store
    const int ng = nt * 32 + 8 * wid;
    #pragma unroll
    for (int i = 0; i < 4; i++) {
        const int r0 = m0 + 64 * i + 2 * lane;
        float2 u[8];
        #pragma unroll
        for (int n = 0; n < 8; n++) u[n] = f2_unpack(acc[i][n]);
        float* o0 = &gout[(long)r0 * FEATW + ng];
        float* o1 = o0 + FEATW;
        *(float4*)&o0[0] = make_float4(u[0].x, u[1].x, u[2].x, u[3].x);
        *(float4*)&o0[4] = make_float4(u[4].x, u[5].x, u[6].x, u[7].x);
        *(float4*)&o1[0] = make_float4(u[0].y, u[1].y, u[2].y, u[3].y);
        *(float4*)&o1[4] = make_float4(u[4].y, u[5].y, u[6].y, u[7].y);
    }
}

// ---------------------------------------------------------------------------
// Kernel 1b: combine left|right halves once: g_lr = p0+p1 (+bl on left).
// ---------------------------------------------------------------------------
__global__ __launch_bounds__(256) void combine_kernel(const float* __restrict__ bl)
{
    const int idx = blockIdx.x * 256 + threadIdx.x;    // float4 index over g_lr
    const int row = idx >> 6;
    const int col = (idx & 63) * 4;                    // 0..252
    const long src = (long)row * FEATW + col;
    const float4 a = *(const float4*)&g_part0[src];
    const float4 b = *(const float4*)&g_part1[src];
    float4 r = make_float4(a.x + b.x, a.y + b.y, a.z + b.z, a.w + b.w);
    if (col < 128) {                                   // left: + bl
        const float4 bb = *(const float4*)&bl[col];
        r.x += bb.x; r.y += bb.y; r.z += bb.z; r.w += bb.w;
    }
    *(float4*)&g_lr[(long)row * LRW + col] = r;
}

// ---------------------------------------------------------------------------
// Kernel 2: start/end heads from raw partials (fused sum+bias+relu+dot).
// ---------------------------------------------------------------------------
__global__ __launch_bounds__(256) void startend_kernel(
    const float* __restrict__ bs1, const float* __restrict__ be1,
    const float* __restrict__ Ws2, const float* __restrict__ bs2,
    const float* __restrict__ We2, const float* __restrict__ be2,
    float* __restrict__ out)
{
    const int warp = blockIdx.x * 8 + (threadIdx.x >> 5);
    const int lane = threadIdx.x & 31;
    const float* h0 = &g_part0[warp * FEATW + 256];
    const float* h1 = &g_part1[warp * FEATW + 256];
    float s = 0.f, e = 0.f;
    #pragma unroll
    for (int u = 0; u < 4; u++) {
        const int p = lane + u * 32;
        s += fmaxf(h0[p]       + h1[p]       + bs1[p], 0.f) * Ws2[p];
        e += fmaxf(h0[p + 128] + h1[p + 128] + be1[p], 0.f) * We2[p];
    }
    #pragma unroll
    for (int o = 16; o; o >>= 1) {
        s += __shfl_xor_sync(0xFFFFFFFFu, s, o);
        e += __shfl_xor_sync(0xFFFFFFFFu, e, o);
    }
    if (lane == 0) {
        out[BB * NSEQ * NSEQ + warp]         = s + bs2[0];
        out[BB * NSEQ * NSEQ + MROWS + warp] = e + be2[0];
    }
}

// ---------------------------------------------------------------------------
// Kernel 3: bigram = relu(left[b,j,:] + right[b,i,:]) . Wo + bo
// R10 form EXACTLY (measured 16.7us): thread = one i, 16 j accumulators,
// 128 thr, grid (16 jtiles, 2 itiles, 8 b). right in regs (double-buffered),
// left/Wo broadcast LDS.
// ---------------------------------------------------------------------------
__global__ __launch_bounds__(128) void bigram_kernel(
    const float* __restrict__ Wo, const float* __restrict__ bo,
    float* __restrict__ out)
{
    __shared__ __align__(16) float Ls[2176];   // 16j x 128p; reused 128x17 transpose
    __shared__ __align__(16) float wos[128];

    const int b  = blockIdx.z;
    const int i0 = blockIdx.y * 128;
    const int j0 = blockIdx.x * 16;
    const int tid = threadIdx.x;

    for (int idx = tid; idx < 512; idx += 128) {
        const int r = idx >> 5, c4 = idx & 31;
        *(float4*)&Ls[r * 128 + c4 * 4] =
            *(const float4*)&g_lr[(long)(b * NSEQ + j0 + r) * LRW + c4 * 4];
    }
    wos[tid] = Wo[tid];
    __syncthreads();

    const int i = i0 + tid;
    const float* rrow = &g_lr[(long)(b * NSEQ + i) * LRW + 128];

    ull acc[16];
    #pragma unroll
    for (int j = 0; j < 16; j++) acc[j] = 0ull;

    float4 rc[4], rn[4];
    #pragma unroll
    for (int q = 0; q < 4; q++) rc[q] = *(const float4*)&rrow[q * 4];

    for (int pc = 0; pc < 8; pc++) {
        if (pc < 7) {
            #pragma unroll
            for (int q = 0; q < 4; q++) rn[q] = *(const float4*)&rrow[(pc + 1) * 16 + q * 4];
        }
        const ull* rv = (const ull*)rc;
        const ull* wv = (const ull*)&wos[pc * 16];
        const float* lbase = &Ls[pc * 16];

        #pragma unroll
        for (int up = 0; up < 4; up++) {
            const ull w0 = wv[2 * up], w1 = wv[2 * up + 1];
            const ull r0 = rv[2 * up], r1 = rv[2 * up + 1];
            #pragma unroll
            for (int j = 0; j < 16; j++) {
                const ull* lp = (const ull*)&lbase[j * 128 + 4 * up];  // bcast LDS.128
                ull s0; ADD2(s0, lp[0], r0);
                float2 f0 = f2_unpack(s0);
                f0.x = fmaxf(f0.x, 0.f); f0.y = fmaxf(f0.y, 0.f);
                FMA2(acc[j], f2_pack(f0.x, f0.y), w0, acc[j]);
                ull s1; ADD2(s1, lp[1], r1);
                float2 f1 = f2_unpack(s1);
                f1.x = fmaxf(f1.x, 0.f); f1.y = fmaxf(f1.y, 0.f);
                FMA2(acc[j], f2_pack(f1.x, f1.y), w1, acc[j]);
            }
        }
        #pragma unroll
        for (int q = 0; q < 4; q++) rc[q] = rn[q];
    }

    // transpose through smem for coalesced output stores
    __syncthreads();
    const float bov = bo[0];
    #pragma unroll
    for (int j = 0; j < 16; j++) {
        const float2 a = f2_unpack(acc[j]);
        Ls[tid * 17 + j] = a.x + a.y + bov;
    }
    __syncthreads();
    #pragma unroll
    for (int it = 0; it < 4; it++) {
        const int f4 = it * 128 + tid;
        const int r  = f4 >> 2;
        const int jj = (f4 & 3) * 4;
        float4 v = make_float4(Ls[r * 17 + jj], Ls[r * 17 + jj + 1],
                               Ls[r * 17 + jj + 2], Ls[r * 17 + jj + 3]);
        *(float4*)&out[(long)(b * NSEQ + i0 + r) * NSEQ + j0 + jj] = v;
    }
}

// ---------------------------------------------------------------------------
extern "C" void kernel_launch(void* const* d_in, const int* in_sizes, int n_in,
                              void* d_out, int out_size)
{
    const int*   sent = (const int*)  d_in[0];
    const float* emb  = (const float*)d_in[1];
    const float* Wl   = (const float*)d_in[2];
    const float* bl   = (const float*)d_in[3];
    const float* Wr   = (const float*)d_in[4];
    const float* Wo   = (const float*)d_in[5];
    const float* bo   = (const float*)d_in[6];
    const float* Ws1  = (const float*)d_in[7];
    const float* bs1  = (const float*)d_in[8];
    const float* Ws2  = (const float*)d_in[9];
    const float* bs2  = (const float*)d_in[10];
    const float* We1  = (const float*)d_in[11];
    const float* be1  = (const float*)d_in[12];
    const float* We2  = (const float*)d_in[13];
    const float* be2  = (const float*)d_in[14];
    float* out = (float*)d_out;

    dim3 ggrid(8, 16, 2);
    gemm_kernel<<<ggrid, 128>>>(sent, emb, Wl, Wr, Ws1, We1);

    combine_kernel<<<512, 256>>>(bl);

    startend_kernel<<<256, 256>>>(bs1, be1, Ws2, bs2, We2, be2, out);

    dim3 bgrid(16, 2, 8);
    bigram_kernel<<<bgrid, 128>>>(Wo, bo, out);
}

// round 16
// speedup vs baseline: 1.2711x; 1.2711x over previous
#include <cuda_runtime.h>

#define BB 8
#define NSEQ 256
#define DD 300
#define KHALF 150
#define MROWS (BB*NSEQ)          // 2048
#define FEATW 512                // left | right | hs | he
#define LRW 256                  // compact left|right width

typedef unsigned long long ull;

// K-half partials (raw), compact combined left|right features
__device__ float g_part0[MROWS * FEATW];
__device__ float g_part1[MROWS * FEATW];
__device__ float g_lr   [MROWS * LRW];   // [row][0:128 left+bl | 128:256 right]

// ---- packed f32x2 helpers (sm_100+) --------------------------------------
__device__ __forceinline__ ull f2_pack(float x, float y) {
    ull r; asm("mov.b64 %0, {%1,%2};" : "=l"(r) : "f"(x), "f"(y)); return r;
}
__device__ __forceinline__ float2 f2_unpack(ull v) {
    float2 r; asm("mov.b64 {%0,%1}, %2;" : "=f"(r.x), "=f"(r.y) : "l"(v)); return r;
}
#define FMA2(d,a,b,c) asm("fma.rn.f32x2 %0, %1, %2, %3;" : "=l"(d) : "l"(a), "l"(b), "l"(c))
#define ADD2(d,a,b)   asm("add.rn.f32x2 %0, %1, %2;"     : "=l"(d) : "l"(a), "l"(b))

// ---------------------------------------------------------------------------
// Kernel 1: fused gather + GEMM partials.  [2048 x 150] @ [150 x 512] x2
// R8-EXACT (measured 28.4us): grid (16 m, 8 n, 2 z) = 256 blocks, 256 thr,
// 2 CTAs/SM. BM=128, BN=64, BK=30. f32x2 pairs over M; B duplicated in smem.
// ---------------------------------------------------------------------------
__global__ __launch_bounds__(256, 2) void gemm_kernel(
    const int*   __restrict__ sent, const float* __restrict__ emb,
    const float* __restrict__ Wl,   const float* __restrict__ Wr,
    const float* __restrict__ Ws1,  const float* __restrict__ We1)
{
    const int BK = 30, PADA = 132, PADB = 132;
    __shared__ __align__(16) float As[2][BK * PADA];   // [k][m]      128 used
    __shared__ __align__(16) float Bs[2][BK * PADB];   // [k][2n dup] 128 used
    __shared__ int rowidx[128];

    const int m0  = blockIdx.x * 128;
    const int n0  = blockIdx.y * 64;
    const int z   = blockIdx.z;          // K half
    const int kz  = z * KHALF;
    const int seg = n0 >> 7;             // 0:left 1:right 2:hs 3:he
    const int nl0 = n0 & 127;

    const float* W;
    if      (seg == 0) W = Wl;
    else if (seg == 1) W = Wr;
    else if (seg == 2) W = Ws1;
    else               W = We1;
    float* gout = z ? g_part1 : g_part0;

    const int tid = threadIdx.x;
    if (tid < 128) rowidx[tid] = sent[m0 + tid];
    __syncthreads();

    // register prefetch: A tile 128x30 = 3840 = 15*256; B tile 64x30 = 1920
    float aR[15], bR[8];
    #pragma unroll
    for (int i = 0; i < 15; i++) {
        int idx = i * 256 + tid; int m = idx / 30; int k = idx - m * 30;
        aR[i] = emb[(long)rowidx[m] * DD + kz + k];
    }
    #pragma unroll
    for (int i = 0; i < 8; i++) {
        int idx = i * 256 + tid;
        if (idx < 1920) { int n = idx / 30; int k = idx - n * 30; bR[i] = W[(nl0 + n) * DD + kz + k]; }
    }

    const int lane = tid & 31;
    const int wid  = tid >> 5;           // warp -> 8 n-columns
    ull acc0[8], acc1[8];
    #pragma unroll
    for (int i = 0; i < 8; i++) { acc0[i] = 0ull; acc1[i] = 0ull; }

    for (int t = 0; t < 5; t++) {
        const int c = t & 1;
        #pragma unroll
        for (int i = 0; i < 15; i++) {
            int idx = i * 256 + tid; int m = idx / 30; int k = idx - m * 30;
            As[c][k * PADA + m] = aR[i];
        }
        #pragma unroll
        for (int i = 0; i < 8; i++) {
            int idx = i * 256 + tid;
            if (idx < 1920) { int n = idx / 30; int k = idx - n * 30;
                *(ull*)&Bs[c][k * PADB + 2 * n] = f2_pack(bR[i], bR[i]); }
        }
        __syncthreads();

        if (t < 4) {
            const int k0 = kz + (t + 1) * BK;
            #pragma unroll
            for (int i = 0; i < 15; i++) {
                int idx = i * 256 + tid; int m = idx / 30; int k = idx - m * 30;
                aR[i] = emb[(long)rowidx[m] * DD + k0 + k];
            }
            #pragma unroll
            for (int i = 0; i < 8; i++) {
                int idx = i * 256 + tid;
                if (idx < 1920) { int n = idx / 30; int k = idx - n * 30; bR[i] = W[(nl0 + n) * DD + k0 + k]; }
            }
        }

        #pragma unroll
        for (int k = 0; k < BK; k++) {
            const ull a0 = *(const ull*)&As[c][k * PADA + 2 * lane];       // (m, m+1)
            const ull a1 = *(const ull*)&As[c][k * PADA + 64 + 2 * lane];
            const ulonglong2* bp = (const ulonglong2*)&Bs[c][k * PADB + 16 * wid]; // bcast
            const ulonglong2 b01 = bp[0], b23 = bp[1], b45 = bp[2], b67 = bp[3];
            ull b[8] = {b01.x, b01.y, b23.x, b23.y, b45.x, b45.y, b67.x, b67.y};
            #pragma unroll
            for (int n = 0; n < 8; n++) {
                FMA2(acc0[n], a0, b[n], acc0[n]);
                FMA2(acc1[n], a1, b[n], acc1[n]);
            }
        }
    }

    // epilogue: raw partial store
    #pragma unroll
    for (int half = 0; half < 2; half++) {
        const ull* ac = half ? acc1 : acc0;
        const int mbase = m0 + half * 64 + 2 * lane;
        float2 u[8];
        #pragma unroll
        for (int n = 0; n < 8; n++) u[n] = f2_unpack(ac[n]);
        float* o0 = &gout[(long)mbase * FEATW + n0 + 8 * wid];
        float* o1 = o0 + FEATW;
        *(float4*)&o0[0] = make_float4(u[0].x, u[1].x, u[2].x, u[3].x);
        *(float4*)&o0[4] = make_float4(u[4].x, u[5].x, u[6].x, u[7].x);
        *(float4*)&o1[0] = make_float4(u[0].y, u[1].y, u[2].y, u[3].y);
        *(float4*)&o1[4] = make_float4(u[4].y, u[5].y, u[6].y, u[7].y);
    }
}

// ---------------------------------------------------------------------------
// Kernel 1b: combine left|right halves once: g_lr = p0+p1 (+bl on left).
// ---------------------------------------------------------------------------
__global__ __launch_bounds__(256) void combine_kernel(const float* __restrict__ bl)
{
    const int idx = blockIdx.x * 256 + threadIdx.x;    // float4 index over g_lr
    const int row = idx >> 6;
    const int col = (idx & 63) * 4;                    // 0..252
    const long src = (long)row * FEATW + col;
    const float4 a = *(const float4*)&g_part0[src];
    const float4 b = *(const float4*)&g_part1[src];
    float4 r = make_float4(a.x + b.x, a.y + b.y, a.z + b.z, a.w + b.w);
    if (col < 128) {                                   // left: + bl
        const float4 bb = *(const float4*)&bl[col];
        r.x += bb.x; r.y += bb.y; r.z += bb.z; r.w += bb.w;
    }
    *(float4*)&g_lr[(long)row * LRW + col] = r;
}

// ---------------------------------------------------------------------------
// Kernel 2: start/end heads from raw partials (fused sum+bias+relu+dot).
// ---------------------------------------------------------------------------
__global__ __launch_bounds__(256) void startend_kernel(
    const float* __restrict__ bs1, const float* __restrict__ be1,
    const float* __restrict__ Ws2, const float* __restrict__ bs2,
    const float* __restrict__ We2, const float* __restrict__ be2,
    float* __restrict__ out)
{
    const int warp = blockIdx.x * 8 + (threadIdx.x >> 5);
    const int lane = threadIdx.x & 31;
    const float* h0 = &g_part0[warp * FEATW + 256];
    const float* h1 = &g_part1[warp * FEATW + 256];
    float s = 0.f, e = 0.f;
    #pragma unroll
    for (int u = 0; u < 4; u++) {
        const int p = lane + u * 32;
        s += fmaxf(h0[p]       + h1[p]       + bs1[p], 0.f) * Ws2[p];
        e += fmaxf(h0[p + 128] + h1[p + 128] + be1[p], 0.f) * We2[p];
    }
    #pragma unroll
    for (int o = 16; o; o >>= 1) {
        s += __shfl_xor_sync(0xFFFFFFFFu, s, o);
        e += __shfl_xor_sync(0xFFFFFFFFu, e, o);
    }
    if (lane == 0) {
        out[BB * NSEQ * NSEQ + warp]         = s + bs2[0];
        out[BB * NSEQ * NSEQ + MROWS + warp] = e + be2[0];
    }
}

// ---------------------------------------------------------------------------
// Kernel 3: bigram = relu(left[b,j,:] + right[b,i,:]) . Wo + bo
// NEW: thread = TWO i rows (tid, tid+128) x 8 j -> 16 acc chains (same ILP
// as the 16.7us R10 version) but each broadcast LDS.128 of L feeds BOTH i
// rows: 8 LDS per up-step instead of 16. Block covers all 256 i x 8 j.
// grid (32 jtiles, 1, 8 b) = 256 blocks, 128 thr.
// ---------------------------------------------------------------------------
__global__ __launch_bounds__(128) void bigram_kernel(
    const float* __restrict__ Wo, const float* __restrict__ bo,
    float* __restrict__ out)
{
    __shared__ __align__(16) float Ls[8 * 128];    // 8 j x 128 p
    __shared__ __align__(16) float wos[128];
    __shared__ __align__(16) float Ts[256 * 9];    // transpose buffer (pad 9)

    const int b  = blockIdx.z;
    const int j0 = blockIdx.x * 8;
    const int tid = threadIdx.x;

    // stage left tile [8 j][128 p] (256 float4, 2 per thread)
    for (int idx = tid; idx < 256; idx += 128) {
        const int r = idx >> 5, c4 = idx & 31;
        *(float4*)&Ls[r * 128 + c4 * 4] =
            *(const float4*)&g_lr[(long)(b * NSEQ + j0 + r) * LRW + c4 * 4];
    }
    wos[tid] = Wo[tid];
    __syncthreads();

    const float* rrowA = &g_lr[(long)(b * NSEQ + tid)       * LRW + 128];
    const float* rrowB = &g_lr[(long)(b * NSEQ + tid + 128) * LRW + 128];

    ull acc[2][8];
    #pragma unroll
    for (int ii = 0; ii < 2; ii++)
        #pragma unroll
        for (int j = 0; j < 8; j++) acc[ii][j] = 0ull;

    // right chunk double buffers (16 p = 4 float4 per row per chunk)
    float4 rcA[4], rcB[4], rnA[4], rnB[4];
    #pragma unroll
    for (int q = 0; q < 4; q++) {
        rcA[q] = *(const float4*)&rrowA[q * 4];
        rcB[q] = *(const float4*)&rrowB[q * 4];
    }

    for (int pc = 0; pc < 8; pc++) {
        if (pc < 7) {
            #pragma unroll
            for (int q = 0; q < 4; q++) {
                rnA[q] = *(const float4*)&rrowA[(pc + 1) * 16 + q * 4];
                rnB[q] = *(const float4*)&rrowB[(pc + 1) * 16 + q * 4];
            }
        }
        const ull* rvA = (const ull*)rcA;              // 8 packed pairs (row A)
        const ull* rvB = (const ull*)rcB;              // 8 packed pairs (row B)
        const ull* wv  = (const ull*)&wos[pc * 16];    // bcast
        const float* lbase = &Ls[pc * 16];

        #pragma unroll
        for (int up = 0; up < 4; up++) {
            const ull w0  = wv[2 * up],  w1  = wv[2 * up + 1];
            const ull rA0 = rvA[2 * up], rA1 = rvA[2 * up + 1];
            const ull rB0 = rvB[2 * up], rB1 = rvB[2 * up + 1];
            #pragma unroll
            for (int j = 0; j < 8; j++) {
                const ull* lp = (const ull*)&lbase[j * 128 + 4 * up];  // bcast LDS.128
                const ull l0 = lp[0], l1 = lp[1];
                ull s; float2 f;
                // row A
                ADD2(s, l0, rA0); f = f2_unpack(s);
                f.x = fmaxf(f.x, 0.f); f.y = fmaxf(f.y, 0.f);
                FMA2(acc[0][j], f2_pack(f.x, f.y), w0, acc[0][j]);
                ADD2(s, l1, rA1); f = f2_unpack(s);
                f.x = fmaxf(f.x, 0.f); f.y = fmaxf(f.y, 0.f);
                FMA2(acc[0][j], f2_pack(f.x, f.y), w1, acc[0][j]);
                // row B
                ADD2(s, l0, rB0); f = f2_unpack(s);
                f.x = fmaxf(f.x, 0.f); f.y = fmaxf(f.y, 0.f);
                FMA2(acc[1][j], f2_pack(f.x, f.y), w0, acc[1][j]);
                ADD2(s, l1, rB1); f = f2_unpack(s);
                f.x = fmaxf(f.x, 0.f); f.y = fmaxf(f.y, 0.f);
                FMA2(acc[1][j], f2_pack(f.x, f.y), w1, acc[1][j]);
            }
        }
        #pragma unroll
        for (int q = 0; q < 4; q++) { rcA[q] = rnA[q]; rcB[q] = rnB[q]; }
    }

    // transpose through smem for coalesced output stores
    const float bov = bo[0];
    #pragma unroll
    for (int ii = 0; ii < 2; ii++)
        #pragma unroll
        for (int j = 0; j < 8; j++) {
            const float2 a = f2_unpack(acc[ii][j]);
            Ts[(ii * 128 + tid) * 9 + j] = a.x + a.y + bov;
        }
    __syncthreads();
    // 256 i x 8 j = 512 float4-chunks of 2... write as 512 float4 (2048 floats): 4 iters
    #pragma unroll
    for (int it = 0; it < 4; it++) {
        const int f4 = it * 128 + tid;     // 0..511
        const int r  = f4 >> 1;            // i row 0..255
        const int jj = (f4 & 1) * 4;       // 0 or 4
        float4 v = make_float4(Ts[r * 9 + jj], Ts[r * 9 + jj + 1],
                               Ts[r * 9 + jj + 2], Ts[r * 9 + jj + 3]);
        *(float4*)&out[(long)(b * NSEQ + r) * NSEQ + j0 + jj] = v;
    }
}

// ---------------------------------------------------------------------------
extern "C" void kernel_launch(void* const* d_in, const int* in_sizes, int n_in,
                              void* d_out, int out_size)
{
    const int*   sent = (const int*)  d_in[0];
    const float* emb  = (const float*)d_in[1];
    const float* Wl   = (const float*)d_in[2];
    const float* bl   = (const float*)d_in[3];
    const float* Wr   = (const float*)d_in[4];
    const float* Wo   = (const float*)d_in[5];
    const float* bo   = (const float*)d_in[6];
    const float* Ws1  = (const float*)d_in[7];
    const float* bs1  = (const float*)d_in[8];
    const float* Ws2  = (const float*)d_in[9];
    const float* bs2  = (const float*)d_in[10];
    const float* We1  = (const float*)d_in[11];
    const float* be1  = (const float*)d_in[12];
    const float* We2  = (const float*)d_in[13];
    const float* be2  = (const float*)d_in[14];
    float* out = (float*)d_out;

    dim3 ggrid(16, 8, 2);
    gemm_kernel<<<ggrid, 256>>>(sent, emb, Wl, Wr, Ws1, We1);

    combine_kernel<<<512, 256>>>(bl);

    startend_kernel<<<256, 256>>>(bs1, be1, Ws2, bs2, We2, be2, out);

    dim3 bgrid(32, 1, 8);
    bigram_kernel<<<bgrid, 128>>>(Wo, bo, out);
}

// round 17
// speedup vs baseline: 1.6096x; 1.2663x over previous
#include <cuda_runtime.h>
#include <cuda_bf16.h>

#define BB 8
#define NSEQ 256
#define DD 300
#define MROWS (BB*NSEQ)          // 2048
#define LRW 256
#define KPG 304                  // padded K in global bf16 arrays
#define KPS 88                   // smem k stride (bf16) — conflict-free
#define KC  80                   // k chunk

typedef unsigned long long ull;

// bf16 split operands (+64 pad: last-chunk staging reads 16 elems past row end)
__device__ __nv_bfloat16 g_xh[MROWS * KPG + 64];
__device__ __nv_bfloat16 g_xl[MROWS * KPG + 64];
__device__ __nv_bfloat16 g_wh[512 * KPG + 64];
__device__ __nv_bfloat16 g_wl[512 * KPG + 64];
// final features
__device__ float g_lr[MROWS * LRW];   // [row][0:128 left+bl | 128:256 right]
__device__ float g_h [MROWS * 256];   // [row][0:128 relu(hs) | 128:256 relu(he)]

// ---- packed f32x2 helpers (bigram) ---------------------------------------
__device__ __forceinline__ ull f2_pack(float x, float y) {
    ull r; asm("mov.b64 %0, {%1,%2};" : "=l"(r) : "f"(x), "f"(y)); return r;
}
__device__ __forceinline__ float2 f2_unpack(ull v) {
    float2 r; asm("mov.b64 {%0,%1}, %2;" : "=f"(r.x), "=f"(r.y) : "l"(v)); return r;
}
#define FMA2(d,a,b,c) asm("fma.rn.f32x2 %0, %1, %2, %3;" : "=l"(d) : "l"(a), "l"(b), "l"(c))
#define ADD2(d,a,b)   asm("add.rn.f32x2 %0, %1, %2;"     : "=l"(d) : "l"(a), "l"(b))

#define LDSM4(r, addr) \
    asm volatile("ldmatrix.sync.aligned.m8n8.x4.shared.b16 {%0,%1,%2,%3}, [%4];" \
        : "=r"((r)[0]), "=r"((r)[1]), "=r"((r)[2]), "=r"((r)[3]) : "r"(addr))

#define MMA_BF16(d, a, b) \
    asm volatile("mma.sync.aligned.m16n8k16.row.col.f32.bf16.bf16.f32 " \
        "{%0,%1,%2,%3}, {%4,%5,%6,%7}, {%8,%9}, {%0,%1,%2,%3};" \
        : "+f"((d)[0]), "+f"((d)[1]), "+f"((d)[2]), "+f"((d)[3]) \
        : "r"((a)[0]), "r"((a)[1]), "r"((a)[2]), "r"((a)[3]), "r"((b)[0]), "r"((b)[1]))

// ---------------------------------------------------------------------------
// prep_x: gather emb rows + bf16 hi/lo split, pad K to 304 with zeros.
// grid 1216 x 256 = 2048 rows * 152 bf16-pairs.
// ---------------------------------------------------------------------------
__global__ __launch_bounds__(256) void prep_x(
    const int* __restrict__ sent, const float* __restrict__ emb)
{
    const int idx = blockIdx.x * 256 + threadIdx.x;  // 311296
    const int row = idx / 152, kp = idx % 152;
    const int k = kp * 2;
    const float* src = emb + (long)sent[row] * DD;
    const float x0 = (k     < DD) ? src[k]     : 0.f;
    const float x1 = (k + 1 < DD) ? src[k + 1] : 0.f;
    const __nv_bfloat16 h0 = __float2bfloat16(x0), h1 = __float2bfloat16(x1);
    const __nv_bfloat16 l0 = __float2bfloat16(x0 - __bfloat162float(h0));
    const __nv_bfloat16 l1 = __float2bfloat16(x1 - __bfloat162float(h1));
    *(__nv_bfloat162*)&g_xh[(long)row * KPG + k] = __nv_bfloat162(h0, h1);
    *(__nv_bfloat162*)&g_xl[(long)row * KPG + k] = __nv_bfloat162(l0, l1);
}

// ---------------------------------------------------------------------------
// prep_w: split concat [Wl|Wr|Ws1|We1] -> bf16 hi/lo. grid 304 x 256.
// ---------------------------------------------------------------------------
__global__ __launch_bounds__(256) void prep_w(
    const float* __restrict__ Wl,  const float* __restrict__ Wr,
    const float* __restrict__ Ws1, const float* __restrict__ We1)
{
    const int idx = blockIdx.x * 256 + threadIdx.x;  // 77824
    const int row = idx / 152, kp = idx % 152;
    const int k = kp * 2;
    const int seg = row >> 7;
    const float* W = seg == 0 ? Wl : seg == 1 ? Wr : seg == 2 ? Ws1 : We1;
    const float* src = W + (long)(row & 127) * DD;
    const float x0 = (k     < DD) ? src[k]     : 0.f;
    const float x1 = (k + 1 < DD) ? src[k + 1] : 0.f;
    const __nv_bfloat16 h0 = __float2bfloat16(x0), h1 = __float2bfloat16(x1);
    const __nv_bfloat16 l0 = __float2bfloat16(x0 - __bfloat162float(h0));
    const __nv_bfloat16 l1 = __float2bfloat16(x1 - __bfloat162float(h1));
    *(__nv_bfloat162*)&g_wh[(long)row * KPG + k] = __nv_bfloat162(h0, h1);
    *(__nv_bfloat162*)&g_wl[(long)row * KPG + k] = __nv_bfloat162(l0, l1);
}

// ---------------------------------------------------------------------------
// mma_gemm: [2048 x 304] @ [304 x 512] via m16n8k16 bf16 x3 (hi/lo split).
// grid (32 m, 8 n) = 256 blocks, 128 thr (4 warps). BM=64, BN=64.
// Warp w owns n-cols [16w, 16w+16) = 2 n8 tiles, all 4 m16 tiles.
// Per warp-kstep: 8 LDSM.x4 (A) + 8 LDS.32 (B) + 24 MMA.
// Epilogue fuses bias/relu per segment -> writes g_lr / g_h directly.
// ---------------------------------------------------------------------------
__global__ __launch_bounds__(128) void mma_gemm(
    const float* __restrict__ bl,
    const float* __restrict__ bs1, const float* __restrict__ be1)
{
    __shared__ __align__(16) __nv_bfloat16 sAh[64 * KPS], sAl[64 * KPS];
    __shared__ __align__(16) __nv_bfloat16 sBh[64 * KPS], sBl[64 * KPS];

    const int m0 = blockIdx.x * 64;
    const int n0 = blockIdx.y * 64;
    const int tid = threadIdx.x;
    const int lane = tid & 31;
    const int wid  = tid >> 5;

    float d[4][2][4];
    #pragma unroll
    for (int mt = 0; mt < 4; mt++)
        #pragma unroll
        for (int nt = 0; nt < 2; nt++)
            #pragma unroll
            for (int q = 0; q < 4; q++) d[mt][nt][q] = 0.f;

    // ldmatrix per-lane base: row = lane&15, col-half = lane>>4
    const unsigned sAh0 = (unsigned)__cvta_generic_to_shared(sAh);
    const unsigned sAl0 = (unsigned)__cvta_generic_to_shared(sAl);
    const unsigned lmoff = (unsigned)((lane & 15) * KPS * 2 + (lane >> 4) * 16);

    const int gid = lane >> 2, tig = lane & 3;

    for (int ch = 0; ch < 4; ch++) {
        const int k0 = ch * KC;
        // stage 4 matrices: 64 rows x 80 bf16 as 10 uint4 per row
        for (int i = tid; i < 640; i += 128) {
            const int r = i / 10, u = i % 10;
            const long  gsrc = (long)(m0 + r) * KPG + k0 + u * 8;
            const long  wsrc = (long)(n0 + r) * KPG + k0 + u * 8;
            const int   sdst = r * KPS + u * 8;
            *(uint4*)&sAh[sdst] = *(const uint4*)&g_xh[gsrc];
            *(uint4*)&sAl[sdst] = *(const uint4*)&g_xl[gsrc];
            *(uint4*)&sBh[sdst] = *(const uint4*)&g_wh[wsrc];
            *(uint4*)&sBl[sdst] = *(const uint4*)&g_wl[wsrc];
        }
        __syncthreads();

        const int nks = (ch < 3) ? 5 : 4;
        for (int ks = 0; ks < nks; ks++) {
            const int kk = ks * 16;
            unsigned ah[4][4], al[4][4];
            #pragma unroll
            for (int mt = 0; mt < 4; mt++) {
                const unsigned off = lmoff + (unsigned)(mt * 16 * KPS * 2 + kk * 2);
                LDSM4(ah[mt], sAh0 + off);
                LDSM4(al[mt], sAl0 + off);
            }
            unsigned bh[2][2], blo[2][2];
            #pragma unroll
            for (int nt = 0; nt < 2; nt++) {
                const int bn = wid * 16 + nt * 8 + gid;
                const int o0 = bn * KPS + kk + 2 * tig;
                bh [nt][0] = *(const unsigned*)&sBh[o0];
                bh [nt][1] = *(const unsigned*)&sBh[o0 + 8];
                blo[nt][0] = *(const unsigned*)&sBl[o0];
                blo[nt][1] = *(const unsigned*)&sBl[o0 + 8];
            }
            #pragma unroll
            for (int mt = 0; mt < 4; mt++)
                #pragma unroll
                for (int nt = 0; nt < 2; nt++) {
                    MMA_BF16(d[mt][nt], ah[mt], bh[nt]);   // hi*hi
                    MMA_BF16(d[mt][nt], ah[mt], blo[nt]);  // hi*lo
                    MMA_BF16(d[mt][nt], al[mt], bh[nt]);   // lo*hi
                }
        }
        __syncthreads();
    }

    // epilogue: seg 0 left(+bl)->g_lr, 1 right->g_lr, 2/3 relu(+bias)->g_h
    const int seg = blockIdx.y >> 1;
    #pragma unroll
    for (int mt = 0; mt < 4; mt++) {
        const int r0 = m0 + mt * 16 + gid;
        #pragma unroll
        for (int nt = 0; nt < 2; nt++) {
            const int ncol = n0 + wid * 16 + nt * 8 + 2 * tig;
            const int bcol = ncol & 127;
            float2 c01 = make_float2(d[mt][nt][0], d[mt][nt][1]);
            float2 c23 = make_float2(d[mt][nt][2], d[mt][nt][3]);
            if (seg == 0) {
                const float b0 = bl[bcol], b1 = bl[bcol + 1];
                c01.x += b0; c01.y += b1; c23.x += b0; c23.y += b1;
                *(float2*)&g_lr[(long)r0 * LRW + ncol] = c01;
                *(float2*)&g_lr[(long)(r0 + 8) * LRW + ncol] = c23;
            } else if (seg == 1) {
                *(float2*)&g_lr[(long)r0 * LRW + ncol] = c01;
                *(float2*)&g_lr[(long)(r0 + 8) * LRW + ncol] = c23;
            } else {
                const float* bp = (seg == 2) ? bs1 : be1;
                const float b0 = bp[bcol], b1 = bp[bcol + 1];
                c01.x = fmaxf(c01.x + b0, 0.f); c01.y = fmaxf(c01.y + b1, 0.f);
                c23.x = fmaxf(c23.x + b0, 0.f); c23.y = fmaxf(c23.y + b1, 0.f);
                const int hc = ncol - 256;     // 0..255 across segs 2,3
                *(float2*)&g_h[(long)r0 * 256 + hc] = c01;
                *(float2*)&g_h[(long)(r0 + 8) * 256 + hc] = c23;
            }
        }
    }
}

// ---------------------------------------------------------------------------
// startend: g_h already bias+relu'd; just dot with Ws2/We2.
// ---------------------------------------------------------------------------
__global__ __launch_bounds__(256) void startend_kernel(
    const float* __restrict__ Ws2, const float* __restrict__ bs2,
    const float* __restrict__ We2, const float* __restrict__ be2,
    float* __restrict__ out)
{
    const int warp = blockIdx.x * 8 + (threadIdx.x >> 5);
    const int lane = threadIdx.x & 31;
    const float* h = &g_h[warp * 256];
    float s = 0.f, e = 0.f;
    #pragma unroll
    for (int u = 0; u < 4; u++) {
        const int p = lane + u * 32;
        s += h[p]       * Ws2[p];
        e += h[p + 128] * We2[p];
    }
    #pragma unroll
    for (int o = 16; o; o >>= 1) {
        s += __shfl_xor_sync(0xFFFFFFFFu, s, o);
        e += __shfl_xor_sync(0xFFFFFFFFu, e, o);
    }
    if (lane == 0) {
        out[BB * NSEQ * NSEQ + warp]         = s + bs2[0];
        out[BB * NSEQ * NSEQ + MROWS + warp] = e + be2[0];
    }
}

// ---------------------------------------------------------------------------
// bigram (R10 form, measured ~16.7us): thread = one i, 16 j accumulators.
// ---------------------------------------------------------------------------
__global__ __launch_bounds__(128) void bigram_kernel(
    const float* __restrict__ Wo, const float* __restrict__ bo,
    float* __restrict__ out)
{
    __shared__ __align__(16) float Ls[2176];
    __shared__ __align__(16) float wos[128];

    const int b  = blockIdx.z;
    const int i0 = blockIdx.y * 128;
    const int j0 = blockIdx.x * 16;
    const int tid = threadIdx.x;

    for (int idx = tid; idx < 512; idx += 128) {
        const int r = idx >> 5, c4 = idx & 31;
        *(float4*)&Ls[r * 128 + c4 * 4] =
            *(const float4*)&g_lr[(long)(b * NSEQ + j0 + r) * LRW + c4 * 4];
    }
    wos[tid] = Wo[tid];
    __syncthreads();

    const int i = i0 + tid;
    const float* rrow = &g_lr[(long)(b * NSEQ + i) * LRW + 128];

    ull acc[16];
    #pragma unroll
    for (int j = 0; j < 16; j++) acc[j] = 0ull;

    float4 rc[4], rn[4];
    #pragma unroll
    for (int q = 0; q < 4; q++) rc[q] = *(const float4*)&rrow[q * 4];

    for (int pc = 0; pc < 8; pc++) {
        if (pc < 7) {
            #pragma unroll
            for (int q = 0; q < 4; q++) rn[q] = *(const float4*)&rrow[(pc + 1) * 16 + q * 4];
        }
        const ull* rv = (const ull*)rc;
        const ull* wv = (const ull*)&wos[pc * 16];
        const float* lbase = &Ls[pc * 16];

        #pragma unroll
        for (int up = 0; up < 4; up++) {
            const ull w0 = wv[2 * up], w1 = wv[2 * up + 1];
            const ull r0 = rv[2 * up], r1 = rv[2 * up + 1];
            #pragma unroll
            for (int j = 0; j < 16; j++) {
                const ull* lp = (const ull*)&lbase[j * 128 + 4 * up];
                ull s0; ADD2(s0, lp[0], r0);
                float2 f0 = f2_unpack(s0);
                f0.x = fmaxf(f0.x, 0.f); f0.y = fmaxf(f0.y, 0.f);
                FMA2(acc[j], f2_pack(f0.x, f0.y), w0, acc[j]);
                ull s1; ADD2(s1, lp[1], r1);
                float2 f1 = f2_unpack(s1);
                f1.x = fmaxf(f1.x, 0.f); f1.y = fmaxf(f1.y, 0.f);
                FMA2(acc[j], f2_pack(f1.x, f1.y), w1, acc[j]);
            }
        }
        #pragma unroll
        for (int q = 0; q < 4; q++) rc[q] = rn[q];
    }

    __syncthreads();
    const float bov = bo[0];
    #pragma unroll
    for (int j = 0; j < 16; j++) {
        const float2 a = f2_unpack(acc[j]);
        Ls[tid * 17 + j] = a.x + a.y + bov;
    }
    __syncthreads();
    #pragma unroll
    for (int it = 0; it < 4; it++) {
        const int f4 = it * 128 + tid;
        const int r  = f4 >> 2;
        const int jj = (f4 & 3) * 4;
        float4 v = make_float4(Ls[r * 17 + jj], Ls[r * 17 + jj + 1],
                               Ls[r * 17 + jj + 2], Ls[r * 17 + jj + 3]);
        *(float4*)&out[(long)(b * NSEQ + i0 + r) * NSEQ + j0 + jj] = v;
    }
}

// ---------------------------------------------------------------------------
extern "C" void kernel_launch(void* const* d_in, const int* in_sizes, int n_in,
                              void* d_out, int out_size)
{
    const int*   sent = (const int*)  d_in[0];
    const float* emb  = (const float*)d_in[1];
    const float* Wl   = (const float*)d_in[2];
    const float* bl   = (const float*)d_in[3];
    const float* Wr   = (const float*)d_in[4];
    const float* Wo   = (const float*)d_in[5];
    const float* bo   = (const float*)d_in[6];
    const float* Ws1  = (const float*)d_in[7];
    const float* bs1  = (const float*)d_in[8];
    const float* Ws2  = (const float*)d_in[9];
    const float* bs2  = (const float*)d_in[10];
    const float* We1  = (const float*)d_in[11];
    const float* be1  = (const float*)d_in[12];
    const float* We2  = (const float*)d_in[13];
    const float* be2  = (const float*)d_in[14];
    float* out = (float*)d_out;

    prep_x<<<1216, 256>>>(sent, emb);
    prep_w<<<304, 256>>>(Wl, Wr, Ws1, We1);

    dim3 ggrid(32, 8);
    mma_gemm<<<ggrid, 128>>>(bl, bs1, be1);

    startend_kernel<<<256, 256>>>(Ws2, bs2, We2, be2, out);

    dim3 bgrid(16, 2, 8);
    bigram_kernel<<<bgrid, 128>>>(Wo, bo, out);
}